// round 4
// baseline (speedup 1.0000x reference)
#include <cuda_runtime.h>
#include <cuda_bf16.h>
#include <cstdint>

#define N_ROWS 4096
#define DIM    1024
#define VOCAB  32000

#define BM 256
#define BN 128
#define BK 32
#define NKSTEP (DIM / BK)        // 32
#define STAGES 4

#define LDA_B 80                 // bytes per smem row (32 bf16 + 8 pad)
#define A_STG_BYTES (BM * LDA_B) // 20480
#define B_STG_BYTES (BN * LDA_B) // 10240
#define STG_BYTES (A_STG_BYTES + B_STG_BYTES)  // 30720
#define SMEM_RED  (STAGES * STG_BYTES)         // 122880
#define SMEM_BYTES (SMEM_RED + 128)

// ---- scratch ----
__device__ __align__(16) __nv_bfloat16 g_xb[N_ROWS * DIM];
__device__ __align__(16) __nv_bfloat16 g_wb[VOCAB * DIM];
__device__ float g_sumexp[N_ROWS];
__device__ float g_tgt[N_ROWS];
__device__ float g_sumlogit;
__device__ int   g_y[N_ROWS];
__device__ int   g_yflag;

// ================= helpers =================
__device__ __forceinline__ uint32_t smem_u32(const void* p) {
    uint32_t a;
    asm("{ .reg .u64 t; cvta.to.shared.u64 t, %1; cvt.u32.u64 %0, t; }" : "=r"(a) : "l"(p));
    return a;
}
__device__ __forceinline__ void cp_async16(uint32_t dst, const void* src) {
    asm volatile("cp.async.cg.shared.global [%0], [%1], 16;" :: "r"(dst), "l"(src) : "memory");
}
__device__ __forceinline__ void cp_commit() {
    asm volatile("cp.async.commit_group;" ::: "memory");
}
template<int N>
__device__ __forceinline__ void cp_wait() {
    asm volatile("cp.async.wait_group %0;" :: "n"(N) : "memory");
}
__device__ __forceinline__ void ldm_x4(uint32_t* r, uint32_t addr) {
    asm volatile("ldmatrix.sync.aligned.m8n8.x4.shared.b16 {%0,%1,%2,%3}, [%4];"
                 : "=r"(r[0]), "=r"(r[1]), "=r"(r[2]), "=r"(r[3]) : "r"(addr));
}
__device__ __forceinline__ void mma16816(float* c, const uint32_t* a, uint32_t b0, uint32_t b1) {
    asm volatile(
        "mma.sync.aligned.m16n8k16.row.col.f32.bf16.bf16.f32 "
        "{%0,%1,%2,%3}, {%4,%5,%6,%7}, {%8,%9}, {%0,%1,%2,%3};"
        : "+f"(c[0]), "+f"(c[1]), "+f"(c[2]), "+f"(c[3])
        : "r"(a[0]), "r"(a[1]), "r"(a[2]), "r"(a[3]), "r"(b0), "r"(b1));
}

// ================= setup kernels =================
__global__ void zero_kernel() {
    int i = blockIdx.x * blockDim.x + threadIdx.x;
    if (i < N_ROWS) { g_sumexp[i] = 0.f; g_tgt[i] = 0.f; }
    if (i == 0) { g_sumlogit = 0.f; g_yflag = 0; }
}

__global__ void detect_y_kernel(const unsigned int* __restrict__ y) {
    int found = 0;
    for (int j = threadIdx.x; j < 2048; j += blockDim.x)
        if (y[2 * j + 1] != 0u) found = 1;
    int any = __syncthreads_or(found);
    if (threadIdx.x == 0) g_yflag = any;
}

__global__ void gather_y_kernel(const void* __restrict__ y) {
    int i = blockIdx.x * blockDim.x + threadIdx.x;
    if (i < N_ROWS)
        g_y[i] = g_yflag ? ((const int*)y)[i] : (int)(((const long long*)y)[i]);
}

__global__ void convert_x_kernel(const float4* __restrict__ src) {
    __nv_bfloat162* dst = (__nv_bfloat162*)g_xb;
    int n4 = N_ROWS * DIM / 4;
    int stride = gridDim.x * blockDim.x;
    for (int i = blockIdx.x * blockDim.x + threadIdx.x; i < n4; i += stride) {
        float4 v = src[i];
        dst[2 * i]     = __floats2bfloat162_rn(v.x, v.y);
        dst[2 * i + 1] = __floats2bfloat162_rn(v.z, v.w);
    }
}

__global__ void convert_w_kernel(const float4* __restrict__ src) {
    __nv_bfloat162* dst = (__nv_bfloat162*)g_wb;
    int n4 = VOCAB * DIM / 4;
    int stride = gridDim.x * blockDim.x;
    for (int i = blockIdx.x * blockDim.x + threadIdx.x; i < n4; i += stride) {
        float4 v = src[i];
        dst[2 * i]     = __floats2bfloat162_rn(v.x, v.y);
        dst[2 * i + 1] = __floats2bfloat162_rn(v.z, v.w);
    }
}

// ================= fused GEMM + softmax stats =================
// Grid (VOCAB/BN=250, N_ROWS/BM=16), 512 threads = 16 warps (8 M x 2 N).
// Warp tile 32(M) x 64(N). Accumulators stay in registers; epilogue reduces
// exp/sum/target directly from fragments.
__global__ void __launch_bounds__(512, 1) fused_kernel() {
    extern __shared__ char smem[];
    const uint32_t sb0 = smem_u32(smem);
    const int tid = threadIdx.x;
    const int wid = tid >> 5, lid = tid & 31;
    const int wm = wid & 7;       // 8 M-warps -> 32 rows each
    const int wn = wid >> 3;      // 2 N-warps -> 64 cols each
    const int v0 = blockIdx.x * BN;
    const int m0 = blockIdx.y * BM;

    if (tid == 0) *(float*)(smem + SMEM_RED) = 0.f;

    // ---- producer helper (issue one stage) ----
    auto load_stage = [&](int s, int kstep) {
        const uint32_t stg = sb0 + s * STG_BYTES;
        const int k0 = kstep * BK;
        // A: 256 rows x 4 chunks of 16B = 1024 slots
#pragma unroll
        for (int i = 0; i < 2; i++) {
            int slot = tid + i * 512;
            int r = slot >> 2, ch = slot & 3;
            cp_async16(stg + r * LDA_B + ch * 16,
                       g_xb + (size_t)(m0 + r) * DIM + k0 + ch * 8);
        }
        // B: 128 rows x 4 chunks = 512 slots
        {
            int r = tid >> 2, ch = tid & 3;
            cp_async16(stg + A_STG_BYTES + r * LDA_B + ch * 16,
                       g_wb + (size_t)(v0 + r) * DIM + k0 + ch * 8);
        }
        cp_commit();
    };

    float acc[2][8][4];
#pragma unroll
    for (int mi = 0; mi < 2; mi++)
#pragma unroll
        for (int ni = 0; ni < 8; ni++)
#pragma unroll
            for (int e = 0; e < 4; e++) acc[mi][ni][e] = 0.f;

    // prologue: fill 3 stages
#pragma unroll
    for (int s = 0; s < STAGES - 1; s++) load_stage(s, s);

    const uint32_t a_row = (uint32_t)(wm * 32 + (lid & 15));
    const uint32_t a_colb = (uint32_t)((lid >> 4) * 16);
    const uint32_t b_rbase = (uint32_t)(wn * 64 + (lid & 15));

    for (int k = 0; k < NKSTEP; k++) {
        cp_wait<STAGES - 2>();
        __syncthreads();
        if (k + STAGES - 1 < NKSTEP) load_stage((k + STAGES - 1) & (STAGES - 1), k + STAGES - 1);

        const uint32_t stg = sb0 + (k & (STAGES - 1)) * STG_BYTES;
        const uint32_t Ab = stg;
        const uint32_t Bb = stg + A_STG_BYTES;

#pragma unroll
        for (int kk = 0; kk < 2; kk++) {
            uint32_t a[2][4];
#pragma unroll
            for (int mi = 0; mi < 2; mi++)
                ldm_x4(a[mi], Ab + (a_row + mi * 16) * LDA_B + kk * 32 + a_colb);
#pragma unroll
            for (int ng = 0; ng < 4; ng++) {
                uint32_t b[4];
                ldm_x4(b, Bb + (b_rbase + ng * 16) * LDA_B + kk * 32 + a_colb);
#pragma unroll
                for (int mi = 0; mi < 2; mi++) {
                    mma16816(acc[mi][ng * 2 + 0], a[mi], b[0], b[2]);
                    mma16816(acc[mi][ng * 2 + 1], a[mi], b[1], b[3]);
                }
            }
        }
    }

    // ---- epilogue: reduce directly from accumulators ----
    const int q = lid >> 2;          // quad row index 0..7
    const int qpos = lid & 3;        // col-pair position
    float sl_tot = 0.f;

#pragma unroll
    for (int mi = 0; mi < 2; mi++) {
#pragma unroll
        for (int pair = 0; pair < 2; pair++) {    // rows q and q+8
            const int mrow = m0 + wm * 32 + mi * 16 + q + pair * 8;
            float se = 0.f, sl = 0.f;
#pragma unroll
            for (int ni = 0; ni < 8; ni++) {
                float c0 = acc[mi][ni][pair * 2 + 0];
                float c1 = acc[mi][ni][pair * 2 + 1];
                se += __expf(c0) + __expf(c1);
                sl += c0 + c1;
            }
            sl_tot += sl;
            // quad reduce (lanes differing in bits 0-1 share the row)
            se += __shfl_xor_sync(0xffffffffu, se, 1);
            se += __shfl_xor_sync(0xffffffffu, se, 2);
            if (qpos == 0) atomicAdd(&g_sumexp[mrow], se);

            // target logit
            const int c = g_y[mrow] - v0 - wn * 64;   // 0..63 if in this warp's cols
            if (c >= 0 && c < 64) {
                const int ni = c >> 3, w = c & 7;
                if (qpos == (w >> 1)) {
                    float v = acc[mi][ni][pair * 2 + (w & 1)];
                    g_tgt[mrow] = v;
                }
            }
        }
    }

    // sum of all logits: warp reduce then CTA-combine then 1 global atomic
#pragma unroll
    for (int o = 16; o; o >>= 1) sl_tot += __shfl_xor_sync(0xffffffffu, sl_tot, o);
    if (lid == 0) atomicAdd((float*)(smem + SMEM_RED), sl_tot);
    __syncthreads();
    if (tid == 0) atomicAdd(&g_sumlogit, *(float*)(smem + SMEM_RED));
}

// ================= finalize =================
__global__ void finalize_kernel(float* __restrict__ out) {
    __shared__ float sa[32], sb[32];
    int tid = threadIdx.x;
    float a = 0.f, b = 0.f;
    for (int i = tid; i < N_ROWS; i += blockDim.x) {
        a += logf(g_sumexp[i]);
        b += g_tgt[i];
    }
#pragma unroll
    for (int o = 16; o; o >>= 1) {
        a += __shfl_xor_sync(0xffffffffu, a, o);
        b += __shfl_xor_sync(0xffffffffu, b, o);
    }
    if ((tid & 31) == 0) { sa[tid >> 5] = a; sb[tid >> 5] = b; }
    __syncthreads();
    if (tid < 32) {
        a = sa[tid]; b = sb[tid];
#pragma unroll
        for (int o = 16; o; o >>= 1) {
            a += __shfl_xor_sync(0xffffffffu, a, o);
            b += __shfl_xor_sync(0xffffffffu, b, o);
        }
        if (tid == 0) {
            const float invN = 1.0f / (float)N_ROWS;
            float loss = a * invN - 0.9f * (b * invN)
                       - 0.1f * g_sumlogit / ((float)N_ROWS * (float)VOCAB);
            out[0] = loss;
        }
    }
}

extern "C" void kernel_launch(void* const* d_in, const int* in_sizes, int n_in,
                              void* d_out, int out_size) {
    const float* x = (const float*)d_in[0];
    const float* W = (const float*)d_in[1];
    const void*  y = d_in[2];
    float* out = (float*)d_out;

    (void)cudaFuncSetAttribute(fused_kernel, cudaFuncAttributeMaxDynamicSharedMemorySize, SMEM_BYTES);

    zero_kernel<<<(N_ROWS + 255) / 256, 256>>>();
    detect_y_kernel<<<1, 256>>>((const unsigned int*)y);
    gather_y_kernel<<<(N_ROWS + 255) / 256, 256>>>(y);
    convert_x_kernel<<<148 * 2, 256>>>((const float4*)x);
    convert_w_kernel<<<148 * 8, 256>>>((const float4*)W);

    dim3 grid(VOCAB / BN, N_ROWS / BM);   // 250 x 16 = 4000 CTAs
    fused_kernel<<<grid, 512, SMEM_BYTES>>>();

    finalize_kernel<<<1, 1024>>>(out);
}

// round 6
// speedup vs baseline: 1.6418x; 1.6418x over previous
#include <cuda_runtime.h>
#include <cuda_bf16.h>
#include <cstdint>
#include <cstring>

#define N_ROWS 4096
#define DIM    1024
#define VOCAB  32000

#define BM 128
#define BN 128
#define BK 32
#define NKSTEP (DIM / BK)        // 32
#define STAGES 4

#define LDA_B 80                 // bytes per smem row (32 bf16 + 8 pad)
#define A_STG_BYTES (BM * LDA_B) // 10240
#define B_STG_BYTES (BN * LDA_B) // 10240
#define STG_BYTES (A_STG_BYTES + B_STG_BYTES)  // 20480
#define SMEM_RED  (STAGES * STG_BYTES)         // 81920
#define SMEM_BYTES (SMEM_RED + 128)

// ---- scratch ----
__device__ __align__(16) __nv_bfloat16 g_xb[N_ROWS * DIM];
__device__ __align__(16) __nv_bfloat16 g_wb[VOCAB * DIM];
__device__ float g_sumexp[N_ROWS];
__device__ float g_tgt[N_ROWS];
__device__ float g_sumlogit;
__device__ int   g_y[N_ROWS];

// ================= helpers =================
__device__ __forceinline__ uint32_t smem_u32(const void* p) {
    uint32_t a;
    asm("{ .reg .u64 t; cvta.to.shared.u64 t, %1; cvt.u32.u64 %0, t; }" : "=r"(a) : "l"(p));
    return a;
}
__device__ __forceinline__ uint32_t pack_bf2(float lo, float hi) {
    __nv_bfloat162 t = __floats2bfloat162_rn(lo, hi);
    uint32_t u;
    memcpy(&u, &t, 4);
    return u;
}
__device__ __forceinline__ void cp_async16(uint32_t dst, const void* src) {
    asm volatile("cp.async.cg.shared.global [%0], [%1], 16;" :: "r"(dst), "l"(src) : "memory");
}
__device__ __forceinline__ void cp_commit() {
    asm volatile("cp.async.commit_group;" ::: "memory");
}
template<int N>
__device__ __forceinline__ void cp_wait() {
    asm volatile("cp.async.wait_group %0;" :: "n"(N) : "memory");
}
__device__ __forceinline__ void ldm_x4(uint32_t* r, uint32_t addr) {
    asm volatile("ldmatrix.sync.aligned.m8n8.x4.shared.b16 {%0,%1,%2,%3}, [%4];"
                 : "=r"(r[0]), "=r"(r[1]), "=r"(r[2]), "=r"(r[3]) : "r"(addr));
}
__device__ __forceinline__ void mma16816(float* c, const uint32_t* a, uint32_t b0, uint32_t b1) {
    asm volatile(
        "mma.sync.aligned.m16n8k16.row.col.f32.bf16.bf16.f32 "
        "{%0,%1,%2,%3}, {%4,%5,%6,%7}, {%8,%9}, {%0,%1,%2,%3};"
        : "+f"(c[0]), "+f"(c[1]), "+f"(c[2]), "+f"(c[3])
        : "r"(a[0]), "r"(a[1]), "r"(a[2]), "r"(a[3]), "r"(b0), "r"(b1));
}

// ================= setup (merged: zero + y-detect + y-gather) =================
// Single block. y width detect: if int64, odd 32-bit words of first 4096 words
// are high halves of labels < 32000 => all zero.
__global__ void setup_kernel(const void* __restrict__ y) {
    __shared__ int s_flag;
    const int tid = threadIdx.x;
    int found = 0;
    const unsigned int* yw = (const unsigned int*)y;
    for (int j = tid; j < 2048; j += blockDim.x)
        if (yw[2 * j + 1] != 0u) found = 1;
    int any = __syncthreads_or(found);
    if (tid == 0) { s_flag = any; g_sumlogit = 0.f; }
    __syncthreads();
    const int isI32 = s_flag;
    for (int i = tid; i < N_ROWS; i += blockDim.x) {
        g_sumexp[i] = 0.f;
        g_tgt[i] = 0.f;
        g_y[i] = isI32 ? ((const int*)y)[i] : (int)(((const long long*)y)[i]);
    }
}

// ================= converts (32B loads -> 16B stores) =================
__global__ void convert_x_kernel(const float4* __restrict__ src) {
    uint4* dst = (uint4*)g_xb;
    const int n8 = N_ROWS * DIM / 8;
    const int stride = gridDim.x * blockDim.x;
    for (int i = blockIdx.x * blockDim.x + threadIdx.x; i < n8; i += stride) {
        float4 v0 = src[2 * i], v1 = src[2 * i + 1];
        uint4 o;
        o.x = pack_bf2(v0.x, v0.y);
        o.y = pack_bf2(v0.z, v0.w);
        o.z = pack_bf2(v1.x, v1.y);
        o.w = pack_bf2(v1.z, v1.w);
        dst[i] = o;
    }
}

__global__ void convert_w_kernel(const float4* __restrict__ src) {
    uint4* dst = (uint4*)g_wb;
    const int n8 = VOCAB * DIM / 8;
    const int stride = gridDim.x * blockDim.x;
    for (int i = blockIdx.x * blockDim.x + threadIdx.x; i < n8; i += stride) {
        float4 v0 = src[2 * i], v1 = src[2 * i + 1];
        uint4 o;
        o.x = pack_bf2(v0.x, v0.y);
        o.y = pack_bf2(v0.z, v0.w);
        o.z = pack_bf2(v1.x, v1.y);
        o.w = pack_bf2(v1.z, v1.w);
        dst[i] = o;
    }
}

// ================= fused GEMM + softmax stats =================
// Grid (VOCAB/BN=250, N_ROWS/BM=32), 256 threads = 8 warps (4 M x 2 N).
// Warp tile 32(M) x 64(N); 64 f32 accumulators/thread; 2 CTAs/SM.
__global__ void __launch_bounds__(256, 2) fused_kernel() {
    extern __shared__ char smem[];
    const uint32_t sb0 = smem_u32(smem);
    const int tid = threadIdx.x;
    const int wid = tid >> 5, lid = tid & 31;
    const int wm = wid & 3;       // 4 M-warps -> 32 rows each
    const int wn = wid >> 2;      // 2 N-warps -> 64 cols each
    const int v0 = blockIdx.x * BN;
    const int m0 = blockIdx.y * BM;

    if (tid == 0) *(float*)(smem + SMEM_RED) = 0.f;

    auto load_stage = [&](int s, int kstep) {
        const uint32_t stg = sb0 + s * STG_BYTES;
        const int k0 = kstep * BK;
        // A: 128 rows x 4 chunks of 16B = 512 slots
#pragma unroll
        for (int i = 0; i < 2; i++) {
            int slot = tid + i * 256;
            int r = slot >> 2, ch = slot & 3;
            cp_async16(stg + r * LDA_B + ch * 16,
                       g_xb + (size_t)(m0 + r) * DIM + k0 + ch * 8);
        }
        // B: 128 rows x 4 chunks = 512 slots
#pragma unroll
        for (int i = 0; i < 2; i++) {
            int slot = tid + i * 256;
            int r = slot >> 2, ch = slot & 3;
            cp_async16(stg + A_STG_BYTES + r * LDA_B + ch * 16,
                       g_wb + (size_t)(v0 + r) * DIM + k0 + ch * 8);
        }
        cp_commit();
    };

    float acc[2][8][4];
#pragma unroll
    for (int mi = 0; mi < 2; mi++)
#pragma unroll
        for (int ni = 0; ni < 8; ni++)
#pragma unroll
            for (int e = 0; e < 4; e++) acc[mi][ni][e] = 0.f;

#pragma unroll
    for (int s = 0; s < STAGES - 1; s++) load_stage(s, s);

    const uint32_t a_row  = (uint32_t)(wm * 32 + (lid & 15));
    const uint32_t a_colb = (uint32_t)((lid >> 4) * 16);
    const uint32_t b_rbase = (uint32_t)(wn * 64 + (lid & 15));

    for (int k = 0; k < NKSTEP; k++) {
        cp_wait<STAGES - 2>();
        __syncthreads();
        if (k + STAGES - 1 < NKSTEP) load_stage((k + STAGES - 1) & (STAGES - 1), k + STAGES - 1);

        const uint32_t stg = sb0 + (k & (STAGES - 1)) * STG_BYTES;
        const uint32_t Ab = stg;
        const uint32_t Bb = stg + A_STG_BYTES;

#pragma unroll
        for (int kk = 0; kk < 2; kk++) {
            uint32_t a[2][4];
#pragma unroll
            for (int mi = 0; mi < 2; mi++)
                ldm_x4(a[mi], Ab + (a_row + mi * 16) * LDA_B + kk * 32 + a_colb);
#pragma unroll
            for (int ng = 0; ng < 4; ng++) {
                uint32_t b[4];
                ldm_x4(b, Bb + (b_rbase + ng * 16) * LDA_B + kk * 32 + a_colb);
#pragma unroll
                for (int mi = 0; mi < 2; mi++) {
                    mma16816(acc[mi][ng * 2 + 0], a[mi], b[0], b[2]);
                    mma16816(acc[mi][ng * 2 + 1], a[mi], b[1], b[3]);
                }
            }
        }
    }

    // ---- epilogue: reduce directly from accumulators ----
    const int q = lid >> 2;          // row within 8-row group
    const int qpos = lid & 3;        // col-pair position within n8
    float sl_tot = 0.f;

#pragma unroll
    for (int mi = 0; mi < 2; mi++) {
#pragma unroll
        for (int pair = 0; pair < 2; pair++) {    // rows q and q+8
            const int mrow = m0 + wm * 32 + mi * 16 + q + pair * 8;
            float se = 0.f, sl = 0.f;
#pragma unroll
            for (int ni = 0; ni < 8; ni++) {
                float c0 = acc[mi][ni][pair * 2 + 0];
                float c1 = acc[mi][ni][pair * 2 + 1];
                se += __expf(c0) + __expf(c1);
                sl += c0 + c1;
            }
            sl_tot += sl;
            se += __shfl_xor_sync(0xffffffffu, se, 1);
            se += __shfl_xor_sync(0xffffffffu, se, 2);
            if (qpos == 0) atomicAdd(&g_sumexp[mrow], se);

            const int c = g_y[mrow] - v0 - wn * 64;   // 0..63 if in this warp's cols
            if (c >= 0 && c < 64) {
                const int ni = c >> 3, w = c & 7;
                if (qpos == (w >> 1))
                    g_tgt[mrow] = acc[mi][ni][pair * 2 + (w & 1)];
            }
        }
    }

#pragma unroll
    for (int o = 16; o; o >>= 1) sl_tot += __shfl_xor_sync(0xffffffffu, sl_tot, o);
    if (lid == 0) atomicAdd((float*)(smem + SMEM_RED), sl_tot);
    __syncthreads();
    if (tid == 0) atomicAdd(&g_sumlogit, *(float*)(smem + SMEM_RED));
}

// ================= finalize =================
__global__ void finalize_kernel(float* __restrict__ out) {
    __shared__ float sa[32], sb[32];
    int tid = threadIdx.x;
    float a = 0.f, b = 0.f;
    for (int i = tid; i < N_ROWS; i += blockDim.x) {
        a += logf(g_sumexp[i]);
        b += g_tgt[i];
    }
#pragma unroll
    for (int o = 16; o; o >>= 1) {
        a += __shfl_xor_sync(0xffffffffu, a, o);
        b += __shfl_xor_sync(0xffffffffu, b, o);
    }
    if ((tid & 31) == 0) { sa[tid >> 5] = a; sb[tid >> 5] = b; }
    __syncthreads();
    if (tid < 32) {
        a = sa[tid]; b = sb[tid];
#pragma unroll
        for (int o = 16; o; o >>= 1) {
            a += __shfl_xor_sync(0xffffffffu, a, o);
            b += __shfl_xor_sync(0xffffffffu, b, o);
        }
        if (tid == 0) {
            const float invN = 1.0f / (float)N_ROWS;
            float loss = a * invN - 0.9f * (b * invN)
                       - 0.1f * g_sumlogit / ((float)N_ROWS * (float)VOCAB);
            out[0] = loss;
        }
    }
}

extern "C" void kernel_launch(void* const* d_in, const int* in_sizes, int n_in,
                              void* d_out, int out_size) {
    const float* x = (const float*)d_in[0];
    const float* W = (const float*)d_in[1];
    const void*  y = d_in[2];
    float* out = (float*)d_out;

    (void)cudaFuncSetAttribute(fused_kernel, cudaFuncAttributeMaxDynamicSharedMemorySize, SMEM_BYTES);

    setup_kernel<<<1, 1024>>>(y);
    convert_x_kernel<<<148 * 4, 256>>>((const float4*)x);
    convert_w_kernel<<<148 * 16, 256>>>((const float4*)W);

    dim3 grid(VOCAB / BN, N_ROWS / BM);   // 250 x 32 = 8000 CTAs
    fused_kernel<<<grid, 256, SMEM_BYTES>>>();

    finalize_kernel<<<1, 1024>>>(out);
}

// round 7
// speedup vs baseline: 3.0051x; 1.8304x over previous
#include <cuda_runtime.h>
#include <cuda_fp16.h>
#include <cstdint>
#include <cstring>

#define N_ROWS 4096
#define DIM    1024
#define VOCAB  32000

#define BM 128
#define BN 128
#define BK 64
#define NKSTEP (DIM / BK)        // 16
#define STAGES 3

#define LDA_B 144                // bytes per smem row (64 f16 = 128B + 16 pad)
#define A_STG_BYTES (BM * LDA_B) // 18432
#define B_STG_BYTES (BN * LDA_B) // 18432
#define STG_BYTES (A_STG_BYTES + B_STG_BYTES)  // 36864
#define SMEM_RED  (STAGES * STG_BYTES)         // 110592
#define SMEM_BYTES (SMEM_RED + 128)

// ---- scratch ----
__device__ __align__(16) __half g_xh[N_ROWS * DIM];
__device__ __align__(16) __half g_wh[VOCAB * DIM];
__device__ float g_sumexp[N_ROWS];
__device__ float g_tgt[N_ROWS];
__device__ float g_sumlogit;
__device__ int   g_y[N_ROWS];

// ================= helpers =================
__device__ __forceinline__ uint32_t smem_u32(const void* p) {
    uint32_t a;
    asm("{ .reg .u64 t; cvta.to.shared.u64 t, %1; cvt.u32.u64 %0, t; }" : "=r"(a) : "l"(p));
    return a;
}
__device__ __forceinline__ uint32_t pack_h2(float lo, float hi) {
    __half2 t = __floats2half2_rn(lo, hi);
    uint32_t u;
    memcpy(&u, &t, 4);
    return u;
}
__device__ __forceinline__ void cp_async16(uint32_t dst, const void* src) {
    asm volatile("cp.async.cg.shared.global [%0], [%1], 16;" :: "r"(dst), "l"(src) : "memory");
}
__device__ __forceinline__ void cp_commit() {
    asm volatile("cp.async.commit_group;" ::: "memory");
}
template<int N>
__device__ __forceinline__ void cp_wait() {
    asm volatile("cp.async.wait_group %0;" :: "n"(N) : "memory");
}
__device__ __forceinline__ void ldm_x4(uint32_t* r, uint32_t addr) {
    asm volatile("ldmatrix.sync.aligned.m8n8.x4.shared.b16 {%0,%1,%2,%3}, [%4];"
                 : "=r"(r[0]), "=r"(r[1]), "=r"(r[2]), "=r"(r[3]) : "r"(addr));
}
// f16 accumulate; NON-volatile so ptxas can interleave with ldmatrix
__device__ __forceinline__ void mma16816h(uint32_t* c, const uint32_t* a, uint32_t b0, uint32_t b1) {
    asm("mma.sync.aligned.m16n8k16.row.col.f16.f16.f16.f16 "
        "{%0,%1}, {%2,%3,%4,%5}, {%6,%7}, {%0,%1};"
        : "+r"(c[0]), "+r"(c[1])
        : "r"(a[0]), "r"(a[1]), "r"(a[2]), "r"(a[3]), "r"(b0), "r"(b1));
}

// ================= setup (zero + y-detect + y-gather) =================
__global__ void setup_kernel(const void* __restrict__ y) {
    __shared__ int s_flag;
    const int tid = threadIdx.x;
    int found = 0;
    const unsigned int* yw = (const unsigned int*)y;
    for (int j = tid; j < 2048; j += blockDim.x)
        if (yw[2 * j + 1] != 0u) found = 1;
    int any = __syncthreads_or(found);
    if (tid == 0) { s_flag = any; g_sumlogit = 0.f; }
    __syncthreads();
    const int isI32 = s_flag;
    for (int i = tid; i < N_ROWS; i += blockDim.x) {
        g_sumexp[i] = 0.f;
        g_tgt[i] = 0.f;
        g_y[i] = isI32 ? ((const int*)y)[i] : (int)(((const long long*)y)[i]);
    }
}

// ================= converts (fp32 -> f16) =================
__global__ void convert_x_kernel(const float4* __restrict__ src) {
    uint4* dst = (uint4*)g_xh;
    const int n8 = N_ROWS * DIM / 8;
    const int stride = gridDim.x * blockDim.x;
    for (int i = blockIdx.x * blockDim.x + threadIdx.x; i < n8; i += stride) {
        float4 v0 = src[2 * i], v1 = src[2 * i + 1];
        uint4 o;
        o.x = pack_h2(v0.x, v0.y);
        o.y = pack_h2(v0.z, v0.w);
        o.z = pack_h2(v1.x, v1.y);
        o.w = pack_h2(v1.z, v1.w);
        dst[i] = o;
    }
}

__global__ void convert_w_kernel(const float4* __restrict__ src) {
    uint4* dst = (uint4*)g_wh;
    const int n8 = VOCAB * DIM / 8;
    const int stride = gridDim.x * blockDim.x;
    for (int i = blockIdx.x * blockDim.x + threadIdx.x; i < n8; i += stride) {
        float4 v0 = src[2 * i], v1 = src[2 * i + 1];
        uint4 o;
        o.x = pack_h2(v0.x, v0.y);
        o.y = pack_h2(v0.z, v0.w);
        o.z = pack_h2(v1.x, v1.y);
        o.w = pack_h2(v1.z, v1.w);
        dst[i] = o;
    }
}

// ================= fused GEMM + softmax stats =================
// Grid (250, 32), 256 threads = 8 warps (4 M x 2 N). Warp tile 32x64.
// f16 accumulators (32 regs); 2 CTAs/SM; 3-stage cp.async, BK=64.
__global__ void __launch_bounds__(256, 2) fused_kernel() {
    extern __shared__ char smem[];
    const uint32_t sb0 = smem_u32(smem);
    const int tid = threadIdx.x;
    const int wid = tid >> 5, lid = tid & 31;
    const int wm = wid & 3;
    const int wn = wid >> 2;
    const int v0 = blockIdx.x * BN;
    const int m0 = blockIdx.y * BM;

    if (tid == 0) *(float*)(smem + SMEM_RED) = 0.f;

    auto load_stage = [&](int s, int kstep) {
        const uint32_t stg = sb0 + s * STG_BYTES;
        const int k0 = kstep * BK;
        // A: 128 rows x 8 chunks of 16B = 1024 slots (8 lanes = one 128B line)
#pragma unroll
        for (int i = 0; i < 4; i++) {
            int slot = tid + i * 256;
            int r = slot >> 3, ch = slot & 7;
            cp_async16(stg + r * LDA_B + ch * 16,
                       g_xh + (size_t)(m0 + r) * DIM + k0 + ch * 8);
        }
        // B: 128 rows x 8 chunks = 1024 slots
#pragma unroll
        for (int i = 0; i < 4; i++) {
            int slot = tid + i * 256;
            int r = slot >> 3, ch = slot & 7;
            cp_async16(stg + A_STG_BYTES + r * LDA_B + ch * 16,
                       g_wh + (size_t)(v0 + r) * DIM + k0 + ch * 8);
        }
        cp_commit();
    };

    uint32_t acc[2][8][2];          // f16x2 accumulators
#pragma unroll
    for (int mi = 0; mi < 2; mi++)
#pragma unroll
        for (int ni = 0; ni < 8; ni++) { acc[mi][ni][0] = 0u; acc[mi][ni][1] = 0u; }

    load_stage(0, 0);
    load_stage(1, 1);

    const uint32_t a_row   = (uint32_t)(wm * 32 + (lid & 15));
    const uint32_t a_colb  = (uint32_t)((lid >> 4) * 16);
    const uint32_t b_rbase = (uint32_t)(wn * 64 + (lid & 15));

    int cs = 0;           // compute stage
    int ps = 2, pk = 2;   // next stage slot / kstep to load

    for (int k = 0; k < NKSTEP; k++) {
        cp_wait<1>();
        __syncthreads();
        if (pk < NKSTEP) {
            load_stage(ps, pk);
            pk++;
            ps = (ps == STAGES - 1) ? 0 : ps + 1;
        } else {
            cp_commit();   // empty group keeps wait_group<1> counting exact
        }

        const uint32_t stg = sb0 + cs * STG_BYTES;
        const uint32_t Ab = stg;
        const uint32_t Bb = stg + A_STG_BYTES;
        cs = (cs == STAGES - 1) ? 0 : cs + 1;

#pragma unroll
        for (int kk = 0; kk < 4; kk++) {
            uint32_t a[2][4];
#pragma unroll
            for (int mi = 0; mi < 2; mi++)
                ldm_x4(a[mi], Ab + (a_row + mi * 16) * LDA_B + kk * 32 + a_colb);
#pragma unroll
            for (int ng = 0; ng < 4; ng++) {
                uint32_t b[4];
                ldm_x4(b, Bb + (b_rbase + ng * 16) * LDA_B + kk * 32 + a_colb);
#pragma unroll
                for (int mi = 0; mi < 2; mi++) {
                    mma16816h(acc[mi][ng * 2 + 0], a[mi], b[0], b[2]);
                    mma16816h(acc[mi][ng * 2 + 1], a[mi], b[1], b[3]);
                }
            }
        }
    }

    // ---- epilogue: reduce directly from f16 accumulators ----
    const int q = lid >> 2;
    const int qpos = lid & 3;
    float sl_tot = 0.f;

#pragma unroll
    for (int mi = 0; mi < 2; mi++) {
#pragma unroll
        for (int pair = 0; pair < 2; pair++) {
            const int mrow = m0 + wm * 32 + mi * 16 + q + pair * 8;
            float se = 0.f, sl = 0.f;
#pragma unroll
            for (int ni = 0; ni < 8; ni++) {
                __half2 h;
                memcpy(&h, &acc[mi][ni][pair], 4);
                float2 v = __half22float2(h);
                se += __expf(v.x) + __expf(v.y);
                sl += v.x + v.y;
            }
            sl_tot += sl;
            se += __shfl_xor_sync(0xffffffffu, se, 1);
            se += __shfl_xor_sync(0xffffffffu, se, 2);
            if (qpos == 0) atomicAdd(&g_sumexp[mrow], se);

            const int c = g_y[mrow] - v0 - wn * 64;
            if (c >= 0 && c < 64) {
                const int ni = c >> 3, w = c & 7;
                if (qpos == (w >> 1)) {
                    __half2 h;
                    memcpy(&h, &acc[mi][ni][pair], 4);
                    float2 v = __half22float2(h);
                    g_tgt[mrow] = (w & 1) ? v.y : v.x;
                }
            }
        }
    }

#pragma unroll
    for (int o = 16; o; o >>= 1) sl_tot += __shfl_xor_sync(0xffffffffu, sl_tot, o);
    if (lid == 0) atomicAdd((float*)(smem + SMEM_RED), sl_tot);
    __syncthreads();
    if (tid == 0) atomicAdd(&g_sumlogit, *(float*)(smem + SMEM_RED));
}

// ================= finalize =================
__global__ void finalize_kernel(float* __restrict__ out) {
    __shared__ float sa[32], sb[32];
    int tid = threadIdx.x;
    float a = 0.f, b = 0.f;
    for (int i = tid; i < N_ROWS; i += blockDim.x) {
        a += logf(g_sumexp[i]);
        b += g_tgt[i];
    }
#pragma unroll
    for (int o = 16; o; o >>= 1) {
        a += __shfl_xor_sync(0xffffffffu, a, o);
        b += __shfl_xor_sync(0xffffffffu, b, o);
    }
    if ((tid & 31) == 0) { sa[tid >> 5] = a; sb[tid >> 5] = b; }
    __syncthreads();
    if (tid < 32) {
        a = sa[tid]; b = sb[tid];
#pragma unroll
        for (int o = 16; o; o >>= 1) {
            a += __shfl_xor_sync(0xffffffffu, a, o);
            b += __shfl_xor_sync(0xffffffffu, b, o);
        }
        if (tid == 0) {
            const float invN = 1.0f / (float)N_ROWS;
            float loss = a * invN - 0.9f * (b * invN)
                       - 0.1f * g_sumlogit / ((float)N_ROWS * (float)VOCAB);
            out[0] = loss;
        }
    }
}

extern "C" void kernel_launch(void* const* d_in, const int* in_sizes, int n_in,
                              void* d_out, int out_size) {
    const float* x = (const float*)d_in[0];
    const float* W = (const float*)d_in[1];
    const void*  y = d_in[2];
    float* out = (float*)d_out;

    (void)cudaFuncSetAttribute(fused_kernel, cudaFuncAttributeMaxDynamicSharedMemorySize, SMEM_BYTES);

    setup_kernel<<<1, 1024>>>(y);
    convert_x_kernel<<<148 * 4, 256>>>((const float4*)x);
    convert_w_kernel<<<148 * 16, 256>>>((const float4*)W);

    dim3 grid(VOCAB / BN, N_ROWS / BM);   // 250 x 32 = 8000 CTAs
    fused_kernel<<<grid, 256, SMEM_BYTES>>>();

    finalize_kernel<<<1, 1024>>>(out);
}